// round 3
// baseline (speedup 1.0000x reference)
#include <cuda_runtime.h>
#include <cstdint>

// Problem dims (fixed by the dataset)
#define T_STEPS 512
#define BATCH   64
#define IDIM    1024
#define HDIM    1024
#define G4      4096   // 4*H
#define KDIM    1024

// 512 MB scratch for the precomputed x-projection (T*B, 4H).
__device__ float g_Zx[(size_t)T_STEPS * BATCH * G4];
__device__ unsigned g_bar;

__global__ void init_kernel() { g_bar = 0u; }

__device__ __forceinline__ uint32_t f2tf32(float f) {
    uint32_t u;
    asm("cvt.rna.tf32.f32 %0, %1;" : "=r"(u) : "f"(f));
    return u;
}

// Split v into hi (tf32) + lo (tf32 of residual). tf32 bit pattern is a valid
// fp32 with the low 13 mantissa bits cleared, so the residual is exact in fp32.
__device__ __forceinline__ void split_tf32(float v, uint32_t& hi, uint32_t& lo) {
    hi = f2tf32(v);
    float r = v - __uint_as_float(hi);
    lo = f2tf32(r);
}

__device__ __forceinline__ void mma8(float* c, const uint32_t* a, const uint32_t* b) {
    asm volatile(
        "mma.sync.aligned.m16n8k8.row.col.f32.tf32.tf32.f32 "
        "{%0,%1,%2,%3},{%4,%5,%6,%7},{%8,%9},{%0,%1,%2,%3};\n"
        : "+f"(c[0]), "+f"(c[1]), "+f"(c[2]), "+f"(c[3])
        : "r"(a[0]), "r"(a[1]), "r"(a[2]), "r"(a[3]), "r"(b[0]), "r"(b[1]));
}

__device__ __forceinline__ float sigmf(float x) { return 1.0f / (1.0f + expf(-x)); }

// ===================== Phase 1: Z_x = x @ w_ih^T + bias =====================
// 3xTF32: acc = Ah*Bh + Ah*Bl + Al*Bh  (error ~2^-22 per element)
// Tile: BM=128, BN=128, BK=16. 8 warps, warp tile 64x32 (4x4 m16n8k8).
__global__ void __launch_bounds__(256)
xproj_kernel(const float* __restrict__ x, const float* __restrict__ w_ih,
             const float* __restrict__ b_ih, const float* __restrict__ b_hh,
             const int* __restrict__ biasflag) {
    const int BK = 16;
    __shared__ uint32_t sAh[128][BK + 1];
    __shared__ uint32_t sAl[128][BK + 1];
    __shared__ uint32_t sBh[128][BK + 1];
    __shared__ uint32_t sBl[128][BK + 1];

    int tid = threadIdx.x, warp = tid >> 5, lane = tid & 31;
    int g = lane >> 2, tg = lane & 3;
    int wm = warp >> 2;   // 0..1  (64-row half)
    int wn = warp & 3;    // 0..3  (32-col strip)
    int m_base = blockIdx.y * 128;
    int n_base = blockIdx.x * 128;

    float acc[4][4][4] = {};

    for (int k0 = 0; k0 < KDIM; k0 += BK) {
#pragma unroll
        for (int it = 0; it < 2; it++) {
            int i = tid + it * 256;            // 512 float4 per operand tile
            int row = i >> 2, c4 = i & 3;
            float4 va = *(const float4*)(x + (size_t)(m_base + row) * KDIM + k0 + c4 * 4);
            split_tf32(va.x, sAh[row][c4 * 4 + 0], sAl[row][c4 * 4 + 0]);
            split_tf32(va.y, sAh[row][c4 * 4 + 1], sAl[row][c4 * 4 + 1]);
            split_tf32(va.z, sAh[row][c4 * 4 + 2], sAl[row][c4 * 4 + 2]);
            split_tf32(va.w, sAh[row][c4 * 4 + 3], sAl[row][c4 * 4 + 3]);
            float4 vb = *(const float4*)(w_ih + (size_t)(n_base + row) * KDIM + k0 + c4 * 4);
            split_tf32(vb.x, sBh[row][c4 * 4 + 0], sBl[row][c4 * 4 + 0]);
            split_tf32(vb.y, sBh[row][c4 * 4 + 1], sBl[row][c4 * 4 + 1]);
            split_tf32(vb.z, sBh[row][c4 * 4 + 2], sBl[row][c4 * 4 + 2]);
            split_tf32(vb.w, sBh[row][c4 * 4 + 3], sBl[row][c4 * 4 + 3]);
        }
        __syncthreads();

#pragma unroll
        for (int kk = 0; kk < 2; kk++) {
            uint32_t afh[4][4], afl[4][4], bfh[4][2], bfl[4][2];
#pragma unroll
            for (int mi = 0; mi < 4; mi++) {
                int r = wm * 64 + mi * 16;
                afh[mi][0] = sAh[r + g][kk * 8 + tg];
                afh[mi][1] = sAh[r + g + 8][kk * 8 + tg];
                afh[mi][2] = sAh[r + g][kk * 8 + tg + 4];
                afh[mi][3] = sAh[r + g + 8][kk * 8 + tg + 4];
                afl[mi][0] = sAl[r + g][kk * 8 + tg];
                afl[mi][1] = sAl[r + g + 8][kk * 8 + tg];
                afl[mi][2] = sAl[r + g][kk * 8 + tg + 4];
                afl[mi][3] = sAl[r + g + 8][kk * 8 + tg + 4];
            }
#pragma unroll
            for (int ni = 0; ni < 4; ni++) {
                int rn = wn * 32 + ni * 8 + g;
                bfh[ni][0] = sBh[rn][kk * 8 + tg];
                bfh[ni][1] = sBh[rn][kk * 8 + tg + 4];
                bfl[ni][0] = sBl[rn][kk * 8 + tg];
                bfl[ni][1] = sBl[rn][kk * 8 + tg + 4];
            }
#pragma unroll
            for (int mi = 0; mi < 4; mi++)
#pragma unroll
                for (int ni = 0; ni < 4; ni++) {
                    mma8(acc[mi][ni], afl[mi], bfh[ni]);   // cross terms first
                    mma8(acc[mi][ni], afh[mi], bfl[ni]);
                    mma8(acc[mi][ni], afh[mi], bfh[ni]);
                }
        }
        __syncthreads();
    }

    int bflag = *biasflag;
#pragma unroll
    for (int mi = 0; mi < 4; mi++) {
#pragma unroll
        for (int ni = 0; ni < 4; ni++) {
            int row0 = m_base + wm * 64 + mi * 16 + g;
            int col0 = n_base + wn * 32 + ni * 8 + 2 * tg;
            float bs0 = bflag ? (b_ih[col0] + b_hh[col0]) : 0.0f;
            float bs1 = bflag ? (b_ih[col0 + 1] + b_hh[col0 + 1]) : 0.0f;
            g_Zx[(size_t)row0 * G4 + col0]           = acc[mi][ni][0] + bs0;
            g_Zx[(size_t)row0 * G4 + col0 + 1]       = acc[mi][ni][1] + bs1;
            g_Zx[(size_t)(row0 + 8) * G4 + col0]     = acc[mi][ni][2] + bs0;
            g_Zx[(size_t)(row0 + 8) * G4 + col0 + 1] = acc[mi][ni][3] + bs1;
        }
    }
}

// ===================== Phase 2: persistent recurrence =====================
// 128 CTAs, CTA bj owns hidden columns j in [bj*8, bj*8+8). Per step:
//   z(64 x 32) = h(64 x 1024) @ w_hh_rows^T   (rows: 4 gates x 8 cols), 3xTF32.
__global__ void __launch_bounds__(256, 1)
recur_kernel(const float* __restrict__ h0, const float* __restrict__ c0,
             const float* __restrict__ w_hh, float* __restrict__ out) {
    const int BK = 32;
    __shared__ uint32_t sAh[64][BK + 1];
    __shared__ uint32_t sAl[64][BK + 1];
    __shared__ uint32_t sBh[32][BK + 1];
    __shared__ uint32_t sBl[32][BK + 1];
    __shared__ float zsm[64][33];

    int tid = threadIdx.x, warp = tid >> 5, lane = tid & 31;
    int g = lane >> 2, tg = lane & 3;
    int wm = warp & 3;    // m-tile 0..3 (16 rows each)
    int wn = warp >> 2;   // n-group 0..1 (16 cols each)
    int j0 = blockIdx.x * 8;
    unsigned nblk = gridDim.x;

    // Per-thread epilogue elements: e0 = tid, e1 = tid + 256 over 512 (b,jj) pairs
    int b0e = tid >> 3, jj0 = tid & 7;
    int b1e = (tid + 256) >> 3, jj1 = (tid + 256) & 7;
    float creg0 = c0[b0e * HDIM + j0 + jj0];
    float creg1 = c0[b1e * HDIM + j0 + jj1];
    float buf0[4] = {0.f, 0.f, 0.f, 0.f};
    float buf1[4] = {0.f, 0.f, 0.f, 0.f};
    float hlast0 = 0.f, hlast1 = 0.f;

    // B operand row this thread loads: row n = tid>>3 (0..31), 1 float4 (c4 = tid&7)
    int brow = tid >> 3;
    int bg = brow >> 3, bjj = brow & 7;
    const float* wrow = w_hh + (size_t)(bg * HDIM + j0 + bjj) * KDIM;
    int bc4 = tid & 7;

    for (int t = 0; t < T_STEPS; t++) {
        const float* hsrc = (t == 0) ? h0 : (out + (size_t)(t - 1) * BATCH * HDIM);
        float acc[2][4] = {};

        for (int k0 = 0; k0 < KDIM; k0 += BK) {
            // A tile: 64 x 32 fp32 -> 512 float4, 2 per thread
#pragma unroll
            for (int it = 0; it < 2; it++) {
                int i = tid + it * 256;
                int row = i >> 3, c4 = i & 7;
                float4 v = *(const float4*)(hsrc + (size_t)row * HDIM + k0 + c4 * 4);
                split_tf32(v.x, sAh[row][c4 * 4 + 0], sAl[row][c4 * 4 + 0]);
                split_tf32(v.y, sAh[row][c4 * 4 + 1], sAl[row][c4 * 4 + 1]);
                split_tf32(v.z, sAh[row][c4 * 4 + 2], sAl[row][c4 * 4 + 2]);
                split_tf32(v.w, sAh[row][c4 * 4 + 3], sAl[row][c4 * 4 + 3]);
            }
            // B tile: 32 x 32 -> 256 float4, 1 per thread
            {
                float4 v = *(const float4*)(wrow + k0 + bc4 * 4);
                split_tf32(v.x, sBh[brow][bc4 * 4 + 0], sBl[brow][bc4 * 4 + 0]);
                split_tf32(v.y, sBh[brow][bc4 * 4 + 1], sBl[brow][bc4 * 4 + 1]);
                split_tf32(v.z, sBh[brow][bc4 * 4 + 2], sBl[brow][bc4 * 4 + 2]);
                split_tf32(v.w, sBh[brow][bc4 * 4 + 3], sBl[brow][bc4 * 4 + 3]);
            }
            __syncthreads();

#pragma unroll
            for (int kk = 0; kk < 4; kk++) {
                uint32_t afh[4], afl[4];
                int r = wm * 16;
                afh[0] = sAh[r + g][kk * 8 + tg];
                afh[1] = sAh[r + g + 8][kk * 8 + tg];
                afh[2] = sAh[r + g][kk * 8 + tg + 4];
                afh[3] = sAh[r + g + 8][kk * 8 + tg + 4];
                afl[0] = sAl[r + g][kk * 8 + tg];
                afl[1] = sAl[r + g + 8][kk * 8 + tg];
                afl[2] = sAl[r + g][kk * 8 + tg + 4];
                afl[3] = sAl[r + g + 8][kk * 8 + tg + 4];
#pragma unroll
                for (int nt = 0; nt < 2; nt++) {
                    int rn = wn * 16 + nt * 8 + g;
                    uint32_t bfh[2] = {sBh[rn][kk * 8 + tg], sBh[rn][kk * 8 + tg + 4]};
                    uint32_t bfl[2] = {sBl[rn][kk * 8 + tg], sBl[rn][kk * 8 + tg + 4]};
                    mma8(acc[nt], afl, bfh);
                    mma8(acc[nt], afh, bfl);
                    mma8(acc[nt], afh, bfh);
                }
            }
            __syncthreads();
        }

        // Scatter z tile to smem so each thread can gather its 4 gates
        {
            int r0 = wm * 16 + g;
#pragma unroll
            for (int nt = 0; nt < 2; nt++) {
                int cc = wn * 16 + nt * 8 + 2 * tg;
                zsm[r0][cc]         = acc[nt][0];
                zsm[r0][cc + 1]     = acc[nt][1];
                zsm[r0 + 8][cc]     = acc[nt][2];
                zsm[r0 + 8][cc + 1] = acc[nt][3];
            }
        }
        __syncthreads();

        // Gate math + skip queue for 2 (b, jj) elements
        {
            size_t zb = (size_t)t * BATCH * G4 + (size_t)b0e * G4 + (j0 + jj0);
            float zi = zsm[b0e][jj0]      + g_Zx[zb];
            float zf = zsm[b0e][8 + jj0]  + g_Zx[zb + 1024];
            float zg = zsm[b0e][16 + jj0] + g_Zx[zb + 2048];
            float zo = zsm[b0e][24 + jj0] + g_Zx[zb + 3072];
            float cn = sigmf(zf) * creg0 + sigmf(zi) * tanhf(zg);
            float h = sigmf(zo) * tanhf(cn);
            int idx = t & 3;
            if (t >= 4) h += buf0[idx];
            buf0[idx] = h;
            creg0 = cn;
            hlast0 = h;
            out[(size_t)t * BATCH * HDIM + b0e * HDIM + j0 + jj0] = h;
        }
        {
            size_t zb = (size_t)t * BATCH * G4 + (size_t)b1e * G4 + (j0 + jj1);
            float zi = zsm[b1e][jj1]      + g_Zx[zb];
            float zf = zsm[b1e][8 + jj1]  + g_Zx[zb + 1024];
            float zg = zsm[b1e][16 + jj1] + g_Zx[zb + 2048];
            float zo = zsm[b1e][24 + jj1] + g_Zx[zb + 3072];
            float cn = sigmf(zf) * creg1 + sigmf(zi) * tanhf(zg);
            float h = sigmf(zo) * tanhf(cn);
            int idx = t & 3;
            if (t >= 4) h += buf1[idx];
            buf1[idx] = h;
            creg1 = cn;
            hlast1 = h;
            out[(size_t)t * BATCH * HDIM + b1e * HDIM + j0 + jj1] = h;
        }

        // Grid barrier: monotonic counter, release arrive + acquire poll
        __syncthreads();
        if (tid == 0) {
            unsigned target = (unsigned)(t + 1) * nblk;
            asm volatile("red.release.gpu.add.u32 [%0], 1;" :: "l"(&g_bar) : "memory");
            unsigned v;
            do {
                asm volatile("ld.acquire.gpu.u32 %0, [%1];" : "=r"(v) : "l"(&g_bar) : "memory");
            } while (v < target);
        }
        __syncthreads();
    }

    // Final h and c appended after out
    float* hfin = out + (size_t)T_STEPS * BATCH * HDIM;
    float* cfin = hfin + BATCH * HDIM;
    hfin[b0e * HDIM + j0 + jj0] = hlast0;
    hfin[b1e * HDIM + j0 + jj1] = hlast1;
    cfin[b0e * HDIM + j0 + jj0] = creg0;
    cfin[b1e * HDIM + j0 + jj1] = creg1;
}

extern "C" void kernel_launch(void* const* d_in, const int* in_sizes, int n_in,
                              void* d_out, int out_size) {
    const float* x    = (const float*)d_in[0];
    const float* h0   = (const float*)d_in[1];
    const float* c0   = (const float*)d_in[2];
    const float* w_ih = (const float*)d_in[3];
    const float* w_hh = (const float*)d_in[4];
    const float* b_ih = (const float*)d_in[5];
    const float* b_hh = (const float*)d_in[6];
    const int* bias   = (const int*)d_in[7];
    float* out = (float*)d_out;

    init_kernel<<<1, 1>>>();
    dim3 g1(G4 / 128, (T_STEPS * BATCH) / 128);  // (32, 256)
    xproj_kernel<<<g1, 256>>>(x, w_ih, b_ih, b_hh, bias);
    recur_kernel<<<128, 256>>>(h0, c0, w_hh, out);
}

// round 5
// speedup vs baseline: 2.7874x; 2.7874x over previous
#include <cuda_runtime.h>
#include <cuda_fp16.h>
#include <cstdint>

#define T_STEPS 512
#define BATCH   64
#define IDIM    1024
#define HDIM    1024
#define G4      4096
#define KDIM    1024
#define KP      (KDIM/2)   // K-pairs per row

// Scratch: x-projection (T*B, 4H) + pre-split w_hh (fp16 hi/mid packed pairs).
__device__ float    g_Zx[(size_t)T_STEPS * BATCH * G4];
__device__ uint32_t g_Wh[(size_t)G4 * KP];
__device__ uint32_t g_Wm[(size_t)G4 * KP];
__device__ unsigned g_bar;

// ---------------------------------------------------------------- helpers
// fp16x2 split of (even, odd) fp32 pair -> packed hi pair + packed mid pair.
__device__ __forceinline__ void split_pair(float e, float o, uint32_t& ph, uint32_t& pm) {
    __half2 hp = __floats2half2_rn(e, o);          // .x (low) = e
    float2 hf = __half22float2(hp);
    __half2 mp = __floats2half2_rn(e - hf.x, o - hf.y);
    ph = *reinterpret_cast<uint32_t*>(&hp);
    pm = *reinterpret_cast<uint32_t*>(&mp);
}

__device__ __forceinline__ void mma16(float* c, const uint32_t* a, const uint32_t* b) {
    asm volatile(
        "mma.sync.aligned.m16n8k16.row.col.f32.f16.f16.f32 "
        "{%0,%1,%2,%3},{%4,%5,%6,%7},{%8,%9},{%0,%1,%2,%3};\n"
        : "+f"(c[0]), "+f"(c[1]), "+f"(c[2]), "+f"(c[3])
        : "r"(a[0]), "r"(a[1]), "r"(a[2]), "r"(a[3]), "r"(b[0]), "r"(b[1]));
}
__device__ __forceinline__ float sigmf(float x) { return 1.0f / (1.0f + expf(-x)); }

// ============ presplit: w_hh -> fp16 (hi, mid) packed K-pairs; reset bar ====
__global__ void __launch_bounds__(256)
presplit_kernel(const float* __restrict__ w_hh) {
    if (blockIdx.x == 0 && threadIdx.x == 0) g_bar = 0u;
    size_t i = ((size_t)blockIdx.x * 256 + threadIdx.x) * 4;  // 4 fp32 = 2 pairs
    float4 v = *(const float4*)(w_hh + i);
    uint2 h, m;
    split_pair(v.x, v.y, h.x, m.x);
    split_pair(v.z, v.w, h.y, m.y);
    *(uint2*)(g_Wh + i / 2) = h;
    *(uint2*)(g_Wm + i / 2) = m;
}

// ============ Phase 1: Z_x = x @ w_ih^T + bias  (fp16x3, m16n8k16) =========
// Tile BM=128, BN=128, BK=32 (16 pairs). 8 warps, warp tile 64x32.
#define XSTR 20   // smem row stride in words (16 pairs + 4 pad, conflict-free)
__global__ void __launch_bounds__(256)
xproj_kernel(const float* __restrict__ x, const float* __restrict__ w_ih,
             const float* __restrict__ b_ih, const float* __restrict__ b_hh,
             const int* __restrict__ biasflag) {
    __shared__ uint32_t sAh[128][XSTR], sAm[128][XSTR];
    __shared__ uint32_t sBh[128][XSTR], sBm[128][XSTR];

    int tid = threadIdx.x, warp = tid >> 5, lane = tid & 31;
    int g = lane >> 2, tg = lane & 3;
    int wm = warp >> 2;   // 0..1 (64-row half)
    int wn = warp & 3;    // 0..3 (32-col strip)
    int m_base = blockIdx.y * 128;
    int n_base = blockIdx.x * 128;

    float acc[4][4][4] = {};

    for (int k0 = 0; k0 < KDIM; k0 += 32) {
        // Stage global loads in registers (overlap with previous chunk's MMA)
        float4 av[4], bv[4];
#pragma unroll
        for (int it = 0; it < 4; it++) {
            int i = tid + it * 256;            // 1024 float4 per operand tile
            int row = i >> 3, c4 = i & 7;
            av[it] = *(const float4*)(x    + (size_t)(m_base + row) * KDIM + k0 + c4 * 4);
            bv[it] = *(const float4*)(w_ih + (size_t)(n_base + row) * KDIM + k0 + c4 * 4);
        }
        __syncthreads();   // previous MMA done reading smem
#pragma unroll
        for (int it = 0; it < 4; it++) {
            int i = tid + it * 256;
            int row = i >> 3, c4 = i & 7;
            split_pair(av[it].x, av[it].y, sAh[row][c4 * 2], sAm[row][c4 * 2]);
            split_pair(av[it].z, av[it].w, sAh[row][c4 * 2 + 1], sAm[row][c4 * 2 + 1]);
            split_pair(bv[it].x, bv[it].y, sBh[row][c4 * 2], sBm[row][c4 * 2]);
            split_pair(bv[it].z, bv[it].w, sBh[row][c4 * 2 + 1], sBm[row][c4 * 2 + 1]);
        }
        __syncthreads();

#pragma unroll
        for (int kk = 0; kk < 2; kk++) {
            uint32_t afh[4][4], afm[4][4];
#pragma unroll
            for (int mi = 0; mi < 4; mi++) {
                int r = wm * 64 + mi * 16;
                afh[mi][0] = sAh[r + g][kk * 8 + tg];
                afh[mi][1] = sAh[r + g + 8][kk * 8 + tg];
                afh[mi][2] = sAh[r + g][kk * 8 + tg + 4];
                afh[mi][3] = sAh[r + g + 8][kk * 8 + tg + 4];
                afm[mi][0] = sAm[r + g][kk * 8 + tg];
                afm[mi][1] = sAm[r + g + 8][kk * 8 + tg];
                afm[mi][2] = sAm[r + g][kk * 8 + tg + 4];
                afm[mi][3] = sAm[r + g + 8][kk * 8 + tg + 4];
            }
#pragma unroll
            for (int ni = 0; ni < 4; ni++) {
                int rn = wn * 32 + ni * 8 + g;
                uint32_t bfh[2] = {sBh[rn][kk * 8 + tg], sBh[rn][kk * 8 + tg + 4]};
                uint32_t bfm[2] = {sBm[rn][kk * 8 + tg], sBm[rn][kk * 8 + tg + 4]};
#pragma unroll
                for (int mi = 0; mi < 4; mi++) {
                    mma16(acc[mi][ni], afh[mi], bfm);   // small terms first
                    mma16(acc[mi][ni], afm[mi], bfh);
                    mma16(acc[mi][ni], afh[mi], bfh);
                }
            }
        }
    }

    int bflag = *biasflag;
#pragma unroll
    for (int mi = 0; mi < 4; mi++) {
#pragma unroll
        for (int ni = 0; ni < 4; ni++) {
            int row0 = m_base + wm * 64 + mi * 16 + g;
            int col0 = n_base + wn * 32 + ni * 8 + 2 * tg;
            float bs0 = bflag ? (b_ih[col0] + b_hh[col0]) : 0.0f;
            float bs1 = bflag ? (b_ih[col0 + 1] + b_hh[col0 + 1]) : 0.0f;
            g_Zx[(size_t)row0 * G4 + col0]           = acc[mi][ni][0] + bs0;
            g_Zx[(size_t)row0 * G4 + col0 + 1]       = acc[mi][ni][1] + bs1;
            g_Zx[(size_t)(row0 + 8) * G4 + col0]     = acc[mi][ni][2] + bs0;
            g_Zx[(size_t)(row0 + 8) * G4 + col0 + 1] = acc[mi][ni][3] + bs1;
        }
    }
}

// ============ Phase 2: persistent recurrence (fp16x3, pipelined) ===========
// 128 CTAs; CTA owns 8 hidden cols x 4 gates (z tile 64x32). BK=32 (16 pairs).
__global__ void __launch_bounds__(256, 1)
recur_kernel(const float* __restrict__ h0, const float* __restrict__ c0,
             float* __restrict__ out) {
    __shared__ uint32_t sAh[64][XSTR], sAm[64][XSTR];
    __shared__ uint32_t sBh[32][XSTR], sBm[32][XSTR];
    __shared__ float zsm[64][33];

    int tid = threadIdx.x, warp = tid >> 5, lane = tid & 31;
    int g = lane >> 2, tg = lane & 3;
    int wm = warp & 3, wn = warp >> 2;
    int j0 = blockIdx.x * 8;
    unsigned nblk = gridDim.x;

    int b0e = tid >> 3, jj0 = tid & 7;
    int b1e = (tid + 256) >> 3, jj1 = (tid + 256) & 7;
    float creg0 = c0[b0e * HDIM + j0 + jj0];
    float creg1 = c0[b1e * HDIM + j0 + jj1];
    float buf0[4] = {0.f, 0.f, 0.f, 0.f};
    float buf1[4] = {0.f, 0.f, 0.f, 0.f};
    float hlast0 = 0.f, hlast1 = 0.f;

    // A-tile slots: 512 float4 per chunk, 2 per thread
    int arow0 = tid >> 3,         ac40 = tid & 7;
    int arow1 = (tid + 256) >> 3, ac41 = (tid + 256) & 7;
    // B-tile slots: 512 pair-words per chunk per array, uint2 per thread
    int brow = tid >> 3;                   // 0..31 (n row)
    int bg = brow >> 3, bjj = brow & 7;
    size_t wpoff = (size_t)(bg * HDIM + j0 + bjj) * KP;  // row base in pairs
    int bpc = (tid & 7) * 2;               // pair col within chunk (0,2,..,14)

    for (int t = 0; t < T_STEPS; t++) {
        const float* hsrc = (t == 0) ? h0 : (out + (size_t)(t - 1) * BATCH * HDIM);

        // Prefetch epilogue Zx early (DRAM stream)
        size_t zb0 = (size_t)t * BATCH * G4 + (size_t)b0e * G4 + (j0 + jj0);
        size_t zb1 = (size_t)t * BATCH * G4 + (size_t)b1e * G4 + (j0 + jj1);
        float zx0[4], zx1[4];
#pragma unroll
        for (int q = 0; q < 4; q++) {
            zx0[q] = g_Zx[zb0 + (size_t)q * 1024];
            zx1[q] = g_Zx[zb1 + (size_t)q * 1024];
        }

        // Pipeline: preload chunk 0 operands
        float4 va0 = *(const float4*)(hsrc + (size_t)arow0 * HDIM + ac40 * 4);
        float4 va1 = *(const float4*)(hsrc + (size_t)arow1 * HDIM + ac41 * 4);
        uint2 wh = *(const uint2*)(g_Wh + wpoff + bpc);
        uint2 wmv = *(const uint2*)(g_Wm + wpoff + bpc);

        float acc[2][4] = {};
        for (int k0 = 0; k0 < KDIM; k0 += 32) {
            split_pair(va0.x, va0.y, sAh[arow0][ac40 * 2], sAm[arow0][ac40 * 2]);
            split_pair(va0.z, va0.w, sAh[arow0][ac40 * 2 + 1], sAm[arow0][ac40 * 2 + 1]);
            split_pair(va1.x, va1.y, sAh[arow1][ac41 * 2], sAm[arow1][ac41 * 2]);
            split_pair(va1.z, va1.w, sAh[arow1][ac41 * 2 + 1], sAm[arow1][ac41 * 2 + 1]);
            sBh[brow][bpc] = wh.x;  sBh[brow][bpc + 1] = wh.y;
            sBm[brow][bpc] = wmv.x; sBm[brow][bpc + 1] = wmv.y;
            __syncthreads();

            if (k0 + 32 < KDIM) {   // prefetch next chunk during MMA
                va0 = *(const float4*)(hsrc + (size_t)arow0 * HDIM + k0 + 32 + ac40 * 4);
                va1 = *(const float4*)(hsrc + (size_t)arow1 * HDIM + k0 + 32 + ac41 * 4);
                wh  = *(const uint2*)(g_Wh + wpoff + (k0 + 32) / 2 + bpc);
                wmv = *(const uint2*)(g_Wm + wpoff + (k0 + 32) / 2 + bpc);
            }

#pragma unroll
            for (int kk = 0; kk < 2; kk++) {
                uint32_t afh[4], afm[4];
                int r = wm * 16;
                afh[0] = sAh[r + g][kk * 8 + tg];
                afh[1] = sAh[r + g + 8][kk * 8 + tg];
                afh[2] = sAh[r + g][kk * 8 + tg + 4];
                afh[3] = sAh[r + g + 8][kk * 8 + tg + 4];
                afm[0] = sAm[r + g][kk * 8 + tg];
                afm[1] = sAm[r + g + 8][kk * 8 + tg];
                afm[2] = sAm[r + g][kk * 8 + tg + 4];
                afm[3] = sAm[r + g + 8][kk * 8 + tg + 4];
#pragma unroll
                for (int nt = 0; nt < 2; nt++) {
                    int rn = wn * 16 + nt * 8 + g;
                    uint32_t bfh[2] = {sBh[rn][kk * 8 + tg], sBh[rn][kk * 8 + tg + 4]};
                    uint32_t bfm[2] = {sBm[rn][kk * 8 + tg], sBm[rn][kk * 8 + tg + 4]};
                    mma16(acc[nt], afh, bfm);
                    mma16(acc[nt], afm, bfh);
                    mma16(acc[nt], afh, bfh);
                }
            }
            __syncthreads();
        }

        // Scatter z tile to smem so each thread can gather its 4 gates
        {
            int r0 = wm * 16 + g;
#pragma unroll
            for (int nt = 0; nt < 2; nt++) {
                int cc = wn * 16 + nt * 8 + 2 * tg;
                zsm[r0][cc]         = acc[nt][0];
                zsm[r0][cc + 1]     = acc[nt][1];
                zsm[r0 + 8][cc]     = acc[nt][2];
                zsm[r0 + 8][cc + 1] = acc[nt][3];
            }
        }
        __syncthreads();

        // Gate math + skip queue
        {
            float zi = zsm[b0e][jj0]      + zx0[0];
            float zf = zsm[b0e][8 + jj0]  + zx0[1];
            float zg = zsm[b0e][16 + jj0] + zx0[2];
            float zo = zsm[b0e][24 + jj0] + zx0[3];
            float cn = sigmf(zf) * creg0 + sigmf(zi) * tanhf(zg);
            float h = sigmf(zo) * tanhf(cn);
            int idx = t & 3;
            if (t >= 4) h += buf0[idx];
            buf0[idx] = h;
            creg0 = cn;
            hlast0 = h;
            out[(size_t)t * BATCH * HDIM + b0e * HDIM + j0 + jj0] = h;
        }
        {
            float zi = zsm[b1e][jj1]      + zx1[0];
            float zf = zsm[b1e][8 + jj1]  + zx1[1];
            float zg = zsm[b1e][16 + jj1] + zx1[2];
            float zo = zsm[b1e][24 + jj1] + zx1[3];
            float cn = sigmf(zf) * creg1 + sigmf(zi) * tanhf(zg);
            float h = sigmf(zo) * tanhf(cn);
            int idx = t & 3;
            if (t >= 4) h += buf1[idx];
            buf1[idx] = h;
            creg1 = cn;
            hlast1 = h;
            out[(size_t)t * BATCH * HDIM + b1e * HDIM + j0 + jj1] = h;
        }

        // Grid barrier: monotonic counter, release arrive + acquire poll
        __syncthreads();
        if (tid == 0) {
            unsigned target = (unsigned)(t + 1) * nblk;
            asm volatile("red.release.gpu.add.u32 [%0], 1;" :: "l"(&g_bar) : "memory");
            unsigned v;
            do {
                asm volatile("ld.acquire.gpu.u32 %0, [%1];" : "=r"(v) : "l"(&g_bar) : "memory");
            } while (v < target);
        }
        __syncthreads();
    }

    float* hfin = out + (size_t)T_STEPS * BATCH * HDIM;
    float* cfin = hfin + BATCH * HDIM;
    hfin[b0e * HDIM + j0 + jj0] = hlast0;
    hfin[b1e * HDIM + j0 + jj1] = hlast1;
    cfin[b0e * HDIM + j0 + jj0] = creg0;
    cfin[b1e * HDIM + j0 + jj1] = creg1;
}

extern "C" void kernel_launch(void* const* d_in, const int* in_sizes, int n_in,
                              void* d_out, int out_size) {
    const float* x    = (const float*)d_in[0];
    const float* h0   = (const float*)d_in[1];
    const float* c0   = (const float*)d_in[2];
    const float* w_ih = (const float*)d_in[3];
    const float* w_hh = (const float*)d_in[4];
    const float* b_ih = (const float*)d_in[5];
    const float* b_hh = (const float*)d_in[6];
    const int* bias   = (const int*)d_in[7];
    float* out = (float*)d_out;

    presplit_kernel<<<(G4 * KDIM) / 1024, 256>>>(w_hh);
    dim3 g1(G4 / 128, (T_STEPS * BATCH) / 128);  // (32, 256)
    xproj_kernel<<<g1, 256>>>(x, w_ih, b_ih, b_hh, bias);
    recur_kernel<<<128, 256>>>(h0, c0, out);
}

// round 6
// speedup vs baseline: 3.7751x; 1.3544x over previous
#include <cuda_runtime.h>
#include <cuda_fp16.h>
#include <cstdint>

#define T_STEPS 512
#define BATCH   64
#define IDIM    1024
#define HDIM    1024
#define G4      4096
#define KDIM    1024
#define KP      (KDIM/2)        // K-pairs per row
#define NCTA    128
#define SLOTS   8192            // uint2 fragment slots per CTA per array

// Scratch: x-projection + fragment-ordered w_hh (fp16 hi/mid) + barrier.
__device__ float g_Zx[(size_t)T_STEPS * BATCH * G4];
__device__ uint2 g_WfragH[(size_t)NCTA * SLOTS];
__device__ uint2 g_WfragM[(size_t)NCTA * SLOTS];
__device__ unsigned g_bar;

// ---------------------------------------------------------------- helpers
__device__ __forceinline__ void split_pair(float e, float o, uint32_t& ph, uint32_t& pm) {
    __half2 hp = __floats2half2_rn(e, o);
    float2 hf = __half22float2(hp);
    __half2 mp = __floats2half2_rn(e - hf.x, o - hf.y);
    ph = *reinterpret_cast<uint32_t*>(&hp);
    pm = *reinterpret_cast<uint32_t*>(&mp);
}
__device__ __forceinline__ void mma16(float* c, const uint32_t* a, const uint32_t* b) {
    asm volatile(
        "mma.sync.aligned.m16n8k16.row.col.f32.f16.f16.f32 "
        "{%0,%1,%2,%3},{%4,%5,%6,%7},{%8,%9},{%0,%1,%2,%3};\n"
        : "+f"(c[0]), "+f"(c[1]), "+f"(c[2]), "+f"(c[3])
        : "r"(a[0]), "r"(a[1]), "r"(a[2]), "r"(a[3]), "r"(b[0]), "r"(b[1]));
}
__device__ __forceinline__ float sigmf(float x) { return 1.0f / (1.0f + expf(-x)); }

// ====== wfrag: permute w_hh into per-CTA MMA-fragment order (hi/mid) =======
// slot s (per CTA): q = s>>5, lane = s&31; q = c*16 + kk*4 + wn*2 + nt.
// uint2 = { pair(kk*8+tg), pair(kk*8+tg+4) } of chunk c for B-row wn*16+nt*8+g.
__global__ void __launch_bounds__(256)
wfrag_kernel(const float* __restrict__ w_hh) {
    size_t s = (size_t)blockIdx.x * 256 + threadIdx.x;
    if (s == 0) g_bar = 0u;
    int cta = (int)(s >> 13);
    int r = (int)(s & (SLOTS - 1));
    int lane = r & 31, q = r >> 5;
    int nt = q & 1, wn = (q >> 1) & 1, kk = (q >> 2) & 3, c = q >> 4;
    int g = lane >> 2, tg = lane & 3;
    int row = wn * 16 + nt * 8 + g;                 // B-row within CTA (0..31)
    size_t R = (size_t)((row >> 3) * HDIM + cta * 8 + (row & 7));  // global W row
    int p0 = c * 32 + kk * 8 + tg;                  // pair cols p0, p0+4
    const float* wr = w_hh + R * KDIM;
    uint32_t h0, m0, h1, m1;
    split_pair(wr[2 * p0],     wr[2 * p0 + 1], h0, m0);
    split_pair(wr[2 * p0 + 8], wr[2 * p0 + 9], h1, m1);
    g_WfragH[s] = make_uint2(h0, h1);
    g_WfragM[s] = make_uint2(m0, m1);
}

// ============ Phase 1: Z_x = x @ w_ih^T + bias  (fp16x3, m16n8k16) =========
#define XSTR 20
__global__ void __launch_bounds__(256)
xproj_kernel(const float* __restrict__ x, const float* __restrict__ w_ih,
             const float* __restrict__ b_ih, const float* __restrict__ b_hh,
             const int* __restrict__ biasflag) {
    __shared__ uint32_t sAh[128][XSTR], sAm[128][XSTR];
    __shared__ uint32_t sBh[128][XSTR], sBm[128][XSTR];

    int tid = threadIdx.x, warp = tid >> 5, lane = tid & 31;
    int g = lane >> 2, tg = lane & 3;
    int wm = warp >> 2, wn = warp & 3;
    int m_base = blockIdx.y * 128, n_base = blockIdx.x * 128;

    float acc[4][4][4] = {};

    for (int k0 = 0; k0 < KDIM; k0 += 32) {
        float4 av[4], bv[4];
#pragma unroll
        for (int it = 0; it < 4; it++) {
            int i = tid + it * 256;
            int row = i >> 3, c4 = i & 7;
            av[it] = *(const float4*)(x    + (size_t)(m_base + row) * KDIM + k0 + c4 * 4);
            bv[it] = *(const float4*)(w_ih + (size_t)(n_base + row) * KDIM + k0 + c4 * 4);
        }
        __syncthreads();
#pragma unroll
        for (int it = 0; it < 4; it++) {
            int i = tid + it * 256;
            int row = i >> 3, c4 = i & 7;
            split_pair(av[it].x, av[it].y, sAh[row][c4 * 2], sAm[row][c4 * 2]);
            split_pair(av[it].z, av[it].w, sAh[row][c4 * 2 + 1], sAm[row][c4 * 2 + 1]);
            split_pair(bv[it].x, bv[it].y, sBh[row][c4 * 2], sBm[row][c4 * 2]);
            split_pair(bv[it].z, bv[it].w, sBh[row][c4 * 2 + 1], sBm[row][c4 * 2 + 1]);
        }
        __syncthreads();

#pragma unroll
        for (int kk = 0; kk < 2; kk++) {
            uint32_t afh[4][4], afm[4][4];
#pragma unroll
            for (int mi = 0; mi < 4; mi++) {
                int r = wm * 64 + mi * 16;
                afh[mi][0] = sAh[r + g][kk * 8 + tg];
                afh[mi][1] = sAh[r + g + 8][kk * 8 + tg];
                afh[mi][2] = sAh[r + g][kk * 8 + tg + 4];
                afh[mi][3] = sAh[r + g + 8][kk * 8 + tg + 4];
                afm[mi][0] = sAm[r + g][kk * 8 + tg];
                afm[mi][1] = sAm[r + g + 8][kk * 8 + tg];
                afm[mi][2] = sAm[r + g][kk * 8 + tg + 4];
                afm[mi][3] = sAm[r + g + 8][kk * 8 + tg + 4];
            }
#pragma unroll
            for (int ni = 0; ni < 4; ni++) {
                int rn = wn * 32 + ni * 8 + g;
                uint32_t bfh[2] = {sBh[rn][kk * 8 + tg], sBh[rn][kk * 8 + tg + 4]};
                uint32_t bfm[2] = {sBm[rn][kk * 8 + tg], sBm[rn][kk * 8 + tg + 4]};
#pragma unroll
                for (int mi = 0; mi < 4; mi++) {
                    mma16(acc[mi][ni], afh[mi], bfm);
                    mma16(acc[mi][ni], afm[mi], bfh);
                    mma16(acc[mi][ni], afh[mi], bfh);
                }
            }
        }
    }

    int bflag = *biasflag;
#pragma unroll
    for (int mi = 0; mi < 4; mi++) {
#pragma unroll
        for (int ni = 0; ni < 4; ni++) {
            int row0 = m_base + wm * 64 + mi * 16 + g;
            int col0 = n_base + wn * 32 + ni * 8 + 2 * tg;
            float bs0 = bflag ? (b_ih[col0] + b_hh[col0]) : 0.0f;
            float bs1 = bflag ? (b_ih[col0 + 1] + b_hh[col0 + 1]) : 0.0f;
            g_Zx[(size_t)row0 * G4 + col0]           = acc[mi][ni][0] + bs0;
            g_Zx[(size_t)row0 * G4 + col0 + 1]       = acc[mi][ni][1] + bs1;
            g_Zx[(size_t)(row0 + 8) * G4 + col0]     = acc[mi][ni][2] + bs0;
            g_Zx[(size_t)(row0 + 8) * G4 + col0 + 1] = acc[mi][ni][3] + bs1;
        }
    }
}

// ============ Phase 2: persistent recurrence ================================
// W fragments resident in smem (loaded once). BK=64, double-buffered A,
// one __syncthreads per chunk. 128 CTAs x 256 threads.
#define ASTR 36   // A smem row stride (32 pairs + 4 pad)
extern __shared__ char rsm[];
__global__ void __launch_bounds__(256, 1)
recur_kernel(const float* __restrict__ h0, const float* __restrict__ c0,
             float* __restrict__ out) {
    uint2*    sWfH = (uint2*)rsm;                       // 8192 uint2 = 64KB
    uint2*    sWfM = sWfH + SLOTS;                      // 64KB
    uint32_t* sA   = (uint32_t*)(sWfM + SLOTS);         // [2 buf][2 hi/mid][64][ASTR]
    float*    zsm  = (float*)(sA + 2 * 2 * 64 * ASTR);  // [64][33]
#define SA(buf, hm, row, col) sA[((((buf) * 2 + (hm)) * 64 + (row)) * ASTR) + (col)]

    int tid = threadIdx.x, warp = tid >> 5, lane = tid & 31;
    int g = lane >> 2, tg = lane & 3;
    int wm = warp & 3, wn = warp >> 2;
    int j0 = blockIdx.x * 8;
    unsigned nblk = gridDim.x;

    // Load resident W fragments (once)
    {
        const uint2* gH = g_WfragH + (size_t)blockIdx.x * SLOTS;
        const uint2* gM = g_WfragM + (size_t)blockIdx.x * SLOTS;
        for (int i = tid; i < SLOTS; i += 256) {
            sWfH[i] = gH[i];
            sWfM[i] = gM[i];
        }
    }

    int b0e = tid >> 3, jj0 = tid & 7;
    int b1e = (tid + 256) >> 3, jj1 = (tid + 256) & 7;
    float creg0 = c0[b0e * HDIM + j0 + jj0];
    float creg1 = c0[b1e * HDIM + j0 + jj1];
    float buf0[4] = {0.f, 0.f, 0.f, 0.f};
    float buf1[4] = {0.f, 0.f, 0.f, 0.f};
    float hlast0 = 0.f, hlast1 = 0.f;

    // A-tile slots: 1024 float4 per 64x64 chunk, 4 per thread
    int arow[4], ac4[4];
#pragma unroll
    for (int it = 0; it < 4; it++) {
        int i = tid + it * 256;
        arow[it] = i >> 4;
        ac4[it] = i & 15;
    }

    size_t zb0 = (size_t)b0e * G4 + (j0 + jj0);
    size_t zb1 = (size_t)b1e * G4 + (j0 + jj1);
    float zx0[4], zx1[4];
#pragma unroll
    for (int q = 0; q < 4; q++) {
        zx0[q] = g_Zx[zb0 + (size_t)q * 1024];
        zx1[q] = g_Zx[zb1 + (size_t)q * 1024];
    }
    __syncthreads();   // W fragments visible

    for (int t = 0; t < T_STEPS; t++) {
        const float* hsrc = (t == 0) ? h0 : (out + (size_t)(t - 1) * BATCH * HDIM);

        // Preload chunk 0
        float4 va[4];
#pragma unroll
        for (int it = 0; it < 4; it++)
            va[it] = *(const float4*)(hsrc + (size_t)arow[it] * HDIM + ac4[it] * 4);

        float acc[2][4] = {};
#pragma unroll 1
        for (int c = 0; c < 16; c++) {
            int bsel = c & 1;
#pragma unroll
            for (int it = 0; it < 4; it++) {
                split_pair(va[it].x, va[it].y,
                           SA(bsel, 0, arow[it], ac4[it] * 2),
                           SA(bsel, 1, arow[it], ac4[it] * 2));
                split_pair(va[it].z, va[it].w,
                           SA(bsel, 0, arow[it], ac4[it] * 2 + 1),
                           SA(bsel, 1, arow[it], ac4[it] * 2 + 1));
            }
            __syncthreads();
            if (c < 15) {
                int k0 = (c + 1) * 64;
#pragma unroll
                for (int it = 0; it < 4; it++)
                    va[it] = *(const float4*)(hsrc + (size_t)arow[it] * HDIM + k0 + ac4[it] * 4);
            }
#pragma unroll
            for (int kk = 0; kk < 4; kk++) {
                uint32_t afh[4], afm[4];
                int r = wm * 16;
                afh[0] = SA(bsel, 0, r + g, kk * 8 + tg);
                afh[1] = SA(bsel, 0, r + g + 8, kk * 8 + tg);
                afh[2] = SA(bsel, 0, r + g, kk * 8 + tg + 4);
                afh[3] = SA(bsel, 0, r + g + 8, kk * 8 + tg + 4);
                afm[0] = SA(bsel, 1, r + g, kk * 8 + tg);
                afm[1] = SA(bsel, 1, r + g + 8, kk * 8 + tg);
                afm[2] = SA(bsel, 1, r + g, kk * 8 + tg + 4);
                afm[3] = SA(bsel, 1, r + g + 8, kk * 8 + tg + 4);
#pragma unroll
                for (int nt = 0; nt < 2; nt++) {
                    int fb = (((c * 4 + kk) * 2 + wn) * 2 + nt) * 32 + lane;
                    uint2 bh = sWfH[fb], bm = sWfM[fb];
                    uint32_t bfh[2] = {bh.x, bh.y};
                    uint32_t bfm[2] = {bm.x, bm.y};
                    mma16(acc[nt], afh, bfm);
                    mma16(acc[nt], afm, bfh);
                    mma16(acc[nt], afh, bfh);
                }
            }
        }
        __syncthreads();   // all MMA reads of sA done before zsm phase reuses time

        // Scatter z tile so each thread gathers its 4 gates
        {
            int r0 = wm * 16 + g;
#pragma unroll
            for (int nt = 0; nt < 2; nt++) {
                int cc = wn * 16 + nt * 8 + 2 * tg;
                zsm[r0 * 33 + cc]           = acc[nt][0];
                zsm[r0 * 33 + cc + 1]       = acc[nt][1];
                zsm[(r0 + 8) * 33 + cc]     = acc[nt][2];
                zsm[(r0 + 8) * 33 + cc + 1] = acc[nt][3];
            }
        }
        __syncthreads();

        // Gate math + skip queue
        {
            float zi = zsm[b0e * 33 + jj0]      + zx0[0];
            float zf = zsm[b0e * 33 + 8 + jj0]  + zx0[1];
            float zg = zsm[b0e * 33 + 16 + jj0] + zx0[2];
            float zo = zsm[b0e * 33 + 24 + jj0] + zx0[3];
            float cn = sigmf(zf) * creg0 + sigmf(zi) * tanhf(zg);
            float h = sigmf(zo) * tanhf(cn);
            int idx = t & 3;
            if (t >= 4) h += buf0[idx];
            buf0[idx] = h;
            creg0 = cn;
            hlast0 = h;
            out[(size_t)t * BATCH * HDIM + b0e * HDIM + j0 + jj0] = h;
        }
        {
            float zi = zsm[b1e * 33 + jj1]      + zx1[0];
            float zf = zsm[b1e * 33 + 8 + jj1]  + zx1[1];
            float zg = zsm[b1e * 33 + 16 + jj1] + zx1[2];
            float zo = zsm[b1e * 33 + 24 + jj1] + zx1[3];
            float cn = sigmf(zf) * creg1 + sigmf(zi) * tanhf(zg);
            float h = sigmf(zo) * tanhf(cn);
            int idx = t & 3;
            if (t >= 4) h += buf1[idx];
            buf1[idx] = h;
            creg1 = cn;
            hlast1 = h;
            out[(size_t)t * BATCH * HDIM + b1e * HDIM + j0 + jj1] = h;
        }

        // Prefetch next step's Zx BEFORE the barrier (step-independent data)
        if (t + 1 < T_STEPS) {
            size_t zn = (size_t)(t + 1) * BATCH * G4;
#pragma unroll
            for (int q = 0; q < 4; q++) {
                zx0[q] = g_Zx[zn + zb0 + (size_t)q * 1024];
                zx1[q] = g_Zx[zn + zb1 + (size_t)q * 1024];
            }
        }

        // Grid barrier: monotonic counter, release arrive + acquire poll
        __syncthreads();
        if (tid == 0) {
            unsigned target = (unsigned)(t + 1) * nblk;
            asm volatile("red.release.gpu.add.u32 [%0], 1;" :: "l"(&g_bar) : "memory");
            unsigned v;
            do {
                asm volatile("ld.acquire.gpu.u32 %0, [%1];" : "=r"(v) : "l"(&g_bar) : "memory");
            } while (v < target);
        }
        __syncthreads();
    }

    float* hfin = out + (size_t)T_STEPS * BATCH * HDIM;
    float* cfin = hfin + BATCH * HDIM;
    hfin[b0e * HDIM + j0 + jj0] = hlast0;
    hfin[b1e * HDIM + j0 + jj1] = hlast1;
    cfin[b0e * HDIM + j0 + jj0] = creg0;
    cfin[b1e * HDIM + j0 + jj1] = creg1;
}

extern "C" void kernel_launch(void* const* d_in, const int* in_sizes, int n_in,
                              void* d_out, int out_size) {
    const float* x    = (const float*)d_in[0];
    const float* h0   = (const float*)d_in[1];
    const float* c0   = (const float*)d_in[2];
    const float* w_ih = (const float*)d_in[3];
    const float* w_hh = (const float*)d_in[4];
    const float* b_ih = (const float*)d_in[5];
    const float* b_hh = (const float*)d_in[6];
    const int* bias   = (const int*)d_in[7];
    float* out = (float*)d_out;

    const int RSMEM = SLOTS * 8 * 2 + 2 * 2 * 64 * ASTR * 4 + 64 * 33 * 4;  // 176384
    cudaFuncSetAttribute(recur_kernel, cudaFuncAttributeMaxDynamicSharedMemorySize, RSMEM);

    wfrag_kernel<<<(NCTA * SLOTS) / 256, 256>>>(w_hh);
    dim3 g1(G4 / 128, (T_STEPS * BATCH) / 128);  // (32, 256)
    xproj_kernel<<<g1, 256>>>(x, w_ih, b_ih, b_hh, bias);
    recur_kernel<<<NCTA, 256, RSMEM>>>(h0, c0, out);
}